// round 13
// baseline (speedup 1.0000x reference)
#include <cuda_runtime.h>
#include <math.h>
#include <float.h>

#define N1 16384
#define N2 16384
#define G 128
#define GH (G + 2)                 // 130: 1-cell halo, no bounds checks in hot path
#define NCH (GH * GH)              // 16900
#define NCH4 16912                 // padded for int4 zeroing
#define CAPLOG 6
#define CAP (1 << CAPLOG)          // 64 slots (central cell lambda ~ 23, P(>64) ~ 1e-13)
#define BOX 6.0f
#define CS (2.0f * BOX / (float)G) // 0.09375
#define QNB 512
#define QTPB 128                   // 2048 warps x 8 groups = 16384 = N1
#define SNB 64
#define STPB 256

// Scratch (no allocations -> __device__ globals). Zero-init at load; the last
// query block re-zeros g_cnt/g_done each launch so graph replays start clean.
__device__ int          g_cnt[NCH4];
__device__ float2       g_pts[NCH * CAP];
__device__ float        g_bsum[QNB];
__device__ volatile unsigned int g_done;

__device__ __forceinline__ int cellcoord(float v) {
    int c = (int)floorf((v + BOX) * (1.0f / CS));
    return min(max(c, 0), G - 1) + 1;   // 1..G (interior of halo grid)
}

// Return-less increment -> REDG (no L2 round-trip funnel).
__device__ __forceinline__ void red_inc(volatile unsigned int* p) {
    asm volatile("red.global.gpu.add.u32 [%0], 1;" :: "l"((unsigned int*)p) : "memory");
}

__device__ __forceinline__ void scan_cell(int c, float qx, float qy, float& lb2) {
    int n = min(__ldg(&g_cnt[c]), CAP);
    const float4* __restrict__ p = (const float4*)&g_pts[c << CAPLOG];
    for (int j = 0; j < n; j += 2) {
        float4 v = __ldg(&p[j >> 1]);
        float dx0 = qx - v.x, dy0 = qy - v.y;
        lb2 = fminf(lb2, fmaf(dx0, dx0, dy0 * dy0));
        if (j + 1 < n) {
            float dx1 = qx - v.z, dy1 = qy - v.w;
            lb2 = fminf(lb2, fmaf(dx1, dx1, dy1 * dy1));
        }
    }
}

// ---- Kernel A: scatter pos2 into halo-grid buckets ----
__global__ void __launch_bounds__(STPB) scatter_kernel(const float* __restrict__ pos2) {
    int i = blockIdx.x * STPB + threadIdx.x;
    if (i < N2) {
        float2 p = ((const float2*)pos2)[i];
        int c = cellcoord(p.y) * GH + cellcoord(p.x);
        int slot = atomicAdd(&g_cnt[c], 1);
        if (slot < CAP) g_pts[(c << CAPLOG) + slot] = p;
    }
}

// ---- Kernel B: exact NN queries + reduction + state cleanup ----
__global__ void __launch_bounds__(QTPB) query_kernel(const float* __restrict__ pos1,
                                                     float* __restrict__ out) {
    const int lane = threadIdx.x & 31;
    const int s    = lane & 3;                       // sub-lane in 4-lane group
    const unsigned gmask = 0xFu << (lane & 28);      // 4-lane group shuffle mask
    const unsigned FULL  = 0xFFFFFFFFu;
    const int wid = (blockIdx.x * QTPB + threadIdx.x) >> 5;

    // One query per 4-lane group: 8 per warp, exact cover of N1.
    const int q = wid * 8 + (lane >> 2);
    const float2 qp = ((const float2*)pos1)[q];
    const float qx = qp.x, qy = qp.y;

    // Cell coords + fractional position (exact 2x2 termination bound).
    const float tx = (qx + BOX) * (1.0f / CS);
    const float ty = (qy + BOX) * (1.0f / CS);
    const int cx = min(max((int)floorf(tx), 0), G - 1) + 1;
    const int cy = min(max((int)floorf(ty), 0), G - 1) + 1;
    const float fx = tx - floorf(tx);
    const float fy = ty - floorf(ty);
    const int ox = (fx >= 0.5f) ? 1 : -1;
    const int oy = (fy >= 0.5f) ? 1 : -1;
    const float mx = fmaxf(fx, 1.0f - fx);
    const float my = fmaxf(fy, 1.0f - fy);
    const float thr = CS * fminf(mx, my);            // dist q -> 2x2 block boundary
    const float thr2 = thr * thr;

    // Phase a: nearest 2x2 block, cell-per-lane (one memory epoch).
    float best2 = FLT_MAX;
    {
        const int dx = (s & 1) ? ox : 0;
        const int dy = (s & 2) ? oy : 0;
        scan_cell((cy + dy) * GH + (cx + dx), qx, qy, best2);
    }
    #pragma unroll
    for (int o = 2; o; o >>= 1)
        best2 = fminf(best2, __shfl_xor_sync(gmask, best2, o));

    // Phase b: escalate to full 3x3 if the 2x2 bound fails (rare).
    if (__any_sync(FULL, best2 > thr2)) {
        if (best2 > thr2) {
            #pragma unroll
            for (int t = s; t < 5; t += 4) {
                int dx = (t < 3) ? -ox : ((t == 3) ? 0 : ox);
                int dy = (t < 3) ? ((t - 1) * oy) : -oy;
                scan_cell((cy + dy) * GH + (cx + dx), qx, qy, best2);
            }
        }
        #pragma unroll
        for (int o = 2; o; o >>= 1)
            best2 = fminf(best2, __shfl_xor_sync(gmask, best2, o));
    }

    // Phase c: very rare tail — full-warp annulus expansion per pending query.
    // A point in ring r>=2 is at distance >= (r-1)*CS; after scanning through
    // ring r1, stop once best2 <= (r1*CS)^2.
    {
        unsigned pend = __ballot_sync(FULL, (s == 0) && (best2 > CS * CS));
        while (pend) {
            const int src = __ffs(pend) - 1;
            pend &= pend - 1;
            const float wqx = __shfl_sync(FULL, qx, src);
            const float wqy = __shfl_sync(FULL, qy, src);
            const int   wcx = __shfl_sync(FULL, cx, src);
            const int   wcy = __shfl_sync(FULL, cy, src);
            float wb2 = __shfl_sync(FULL, best2, src);

            int r0 = 2;
            while (r0 < 2 * G) {
                const float dm = (float)(r0 - 1) * CS;
                if (wb2 <= dm * dm) break;
                const int r1 = r0 + 3;
                const int W  = 2 * r1 + 1;
                const int H  = r1 - r0 + 1;
                const int A  = 2 * H * W;
                const int w2 = 2 * H;
                const int ncells = A + (2 * r0 - 1) * w2;

                float lb2 = wb2;
                for (int t = lane; t < ncells; t += 32) {
                    int dx, dy;
                    if (t < A) {
                        int row = t / W, col = t - row * W;
                        dy = (row < H) ? (-r1 + row) : (r0 + row - H);
                        dx = col - r1;
                    } else {
                        int u = t - A;
                        int row = u / w2, col = u - row * w2;
                        dy = -r0 + 1 + row;
                        dx = (col < H) ? (-r1 + col) : (r0 + col - H);
                    }
                    int xx = wcx + dx, yy = wcy + dy;
                    if (xx >= 1 && xx <= G && yy >= 1 && yy <= G)
                        scan_cell(yy * GH + xx, wqx, wqy, lb2);
                }
                #pragma unroll
                for (int o = 16; o; o >>= 1)
                    lb2 = fminf(lb2, __shfl_xor_sync(FULL, lb2, o));
                wb2 = lb2;
                r0 = r1 + 1;
            }
            if (lane == src) best2 = wb2;
        }
    }

    // Warp-level deterministic sum (one contribution per query).
    float v = (s == 0) ? sqrtf(best2) : 0.0f;
    #pragma unroll
    for (int o = 16; o; o >>= 1)
        v += __shfl_xor_sync(FULL, v, o);             // fixed-order butterfly

    __shared__ float wsum[QTPB / 32];
    if (lane == 0) wsum[threadIdx.x >> 5] = v;
    __syncthreads();

    // Publish partial; detect last block via REDG + single poller in block 0.
    if (threadIdx.x == 0) {
        float bs = 0.0f;
        #pragma unroll
        for (int w = 0; w < QTPB / 32; w++) bs += wsum[w];
        g_bsum[blockIdx.x] = bs;
        __threadfence();
        red_inc(&g_done);
    }

    if (blockIdx.x != 0) return;

    // Block 0: wait for all partials, final fixed-order sum, state cleanup.
    if (threadIdx.x == 0) {
        while (g_done < (unsigned int)QNB) __nanosleep(64);
        __threadfence();
    }
    __syncthreads();

    __shared__ float fr[QTPB];
    fr[threadIdx.x] = (g_bsum[threadIdx.x]            + g_bsum[threadIdx.x + QTPB]) +
                      (g_bsum[threadIdx.x + 2 * QTPB] + g_bsum[threadIdx.x + 3 * QTPB]);
    __syncthreads();
    #pragma unroll
    for (int st = QTPB / 2; st > 0; st >>= 1) {
        if (threadIdx.x < st) fr[threadIdx.x] += fr[threadIdx.x + st];
        __syncthreads();
    }
    if (threadIdx.x == 0) {
        out[0] = fr[0] * (1.0f / (float)N1);
        g_done = 0;
    }
    // re-zero cell counters for the next graph replay
    int4* z = (int4*)g_cnt;
    for (int i = threadIdx.x; i < NCH4 / 4; i += QTPB)
        z[i] = make_int4(0, 0, 0, 0);
}

extern "C" void kernel_launch(void* const* d_in, const int* in_sizes, int n_in,
                              void* d_out, int out_size) {
    const float* pos1 = (const float*)d_in[0];
    const float* pos2 = (const float*)d_in[1];

    scatter_kernel<<<SNB, STPB>>>(pos2);
    query_kernel<<<QNB, QTPB>>>(pos1, (float*)d_out);
}